// round 2
// baseline (speedup 1.0000x reference)
#include <cuda_runtime.h>
#include <math.h>

// Problem constants
#define BB 64
#define TT 2048
#define DD 256
#define VV 256

// Scratch (device globals: allocation-free per harness rules)
__device__ float g_WxE[VV * DD];                       // [v][e]  = E[v] @ Wx^T
__device__ float g_GateE[VV * DD];                     // [v][e]  = sigmoid(E[v] @ Wz^T)
__device__ float g_Y[(long long)BB * TT * DD];         // [b][t][d] = h_t * gate_t  (128 MB)

// ---------------------------------------------------------------------------
// Packed fp32x2 helpers (Blackwell): doubles FFMA issue throughput vs 3-reg FFMA
// ---------------------------------------------------------------------------
__device__ __forceinline__ unsigned long long ffma2(unsigned long long a,
                                                    unsigned long long b,
                                                    unsigned long long c) {
    unsigned long long d;
    asm("fma.rn.f32x2 %0, %1, %2, %3;" : "=l"(d) : "l"(a), "l"(b), "l"(c));
    return d;
}
__device__ __forceinline__ unsigned long long packf2(float lo, float hi) {
    unsigned long long d;
    asm("mov.b64 %0, {%1, %2};" : "=l"(d) : "f"(lo), "f"(hi));
    return d;
}
__device__ __forceinline__ float2 unpackf2(unsigned long long v) {
    float lo, hi;
    asm("mov.b64 {%0, %1}, %2;" : "=f"(lo), "=f"(hi) : "l"(v));
    return make_float2(lo, hi);
}

// ---------------------------------------------------------------------------
// Cluster / DSMEM helpers
// ---------------------------------------------------------------------------
__device__ __forceinline__ unsigned smem_u32(const void* p) {
    return (unsigned)__cvta_generic_to_shared(p);
}
__device__ __forceinline__ unsigned mapa_u32(unsigned addr, unsigned rank) {
    unsigned r;
    asm("mapa.shared::cluster.u32 %0, %1, %2;" : "=r"(r) : "r"(addr), "r"(rank));
    return r;
}
__device__ __forceinline__ void st_cluster_f32(unsigned addr, float v) {
    asm volatile("st.shared::cluster.f32 [%0], %1;" :: "r"(addr), "f"(v) : "memory");
}
__device__ __forceinline__ void cluster_arrive() {
    asm volatile("barrier.cluster.arrive.aligned;" ::: "memory");
}
__device__ __forceinline__ void cluster_wait() {
    asm volatile("barrier.cluster.wait.aligned;" ::: "memory");
}
__device__ __forceinline__ unsigned cluster_rank() {
    unsigned r;
    asm("mov.u32 %0, %%cluster_ctarank;" : "=r"(r));
    return r;
}

// ---------------------------------------------------------------------------
// Kernel A: token-indexed projection LUTs.
//   g_WxE[v][e]   = sum_d E[v][d] * Wx[e][d]
//   g_GateE[v][e] = sigmoid(sum_d E[v][d] * Wz[e][d])
// Grid: 32 blocks x 256 threads; each block handles 8 vocab rows.
// ---------------------------------------------------------------------------
__global__ void __launch_bounds__(256) precompute_kernel(
    const float* __restrict__ E, const float* __restrict__ Wx,
    const float* __restrict__ Wz) {
    __shared__ __align__(16) float sE[8][DD];
    const int v0 = blockIdx.x * 8;
    const int tid = threadIdx.x;

    // Load 8 E rows (2048 floats) cooperatively
    for (int i = tid; i < 8 * DD / 4; i += 256)
        ((float4*)&sE[0][0])[i] = ((const float4*)(E + (size_t)v0 * DD))[i];
    __syncthreads();

    const int e = tid;
    float awx[8], awz[8];
#pragma unroll
    for (int v = 0; v < 8; v++) { awx[v] = 0.f; awz[v] = 0.f; }

    const float4* wxr = (const float4*)(Wx + (size_t)e * DD);
    const float4* wzr = (const float4*)(Wz + (size_t)e * DD);
#pragma unroll 4
    for (int dq = 0; dq < DD / 4; dq++) {
        float4 x4 = wxr[dq];
        float4 z4 = wzr[dq];
#pragma unroll
        for (int v = 0; v < 8; v++) {
            float4 e4 = *(const float4*)&sE[v][dq * 4];
            awx[v] = fmaf(x4.x, e4.x, awx[v]);
            awx[v] = fmaf(x4.y, e4.y, awx[v]);
            awx[v] = fmaf(x4.z, e4.z, awx[v]);
            awx[v] = fmaf(x4.w, e4.w, awx[v]);
            awz[v] = fmaf(z4.x, e4.x, awz[v]);
            awz[v] = fmaf(z4.y, e4.y, awz[v]);
            awz[v] = fmaf(z4.z, e4.z, awz[v]);
            awz[v] = fmaf(z4.w, e4.w, awz[v]);
        }
    }
#pragma unroll
    for (int v = 0; v < 8; v++) {
        g_WxE[(size_t)(v0 + v) * DD + e] = awx[v];
        g_GateE[(size_t)(v0 + v) * DD + e] = 1.f / (1.f + expf(-awz[v]));
    }
}

// ---------------------------------------------------------------------------
// Kernel B: the recurrence. One 2-CTA cluster per batch (grid 128, block 256).
// CTA rank r holds Wh rows [r*128, r*128+128) in REGISTERS (fp32).
// Thread t: output row j = r*128 + (t&127), h-segment seg = t>>7 (128 cols).
// Per step: register matvec (f32x2 packed), pair-reduce via smem, tanh,
// write new h half locally + to peer via DSMEM, cluster barrier.
// ---------------------------------------------------------------------------
__global__ void __launch_bounds__(256, 1) __cluster_dims__(2, 1, 1)
rnn_kernel(const int* __restrict__ tokens, const float* __restrict__ Wh) {
    __shared__ __align__(16) float s_h[2][DD];     // double-buffered full h
    __shared__ __align__(16) float s_part[128];    // seg-1 partial sums
    __shared__ __align__(16) int s_tok[TT];        // this batch's tokens

    const unsigned rank = cluster_rank();
    const int b = blockIdx.x >> 1;
    const int tid = threadIdx.x;
    const int seg = tid >> 7;          // which half of h this thread dots
    const int jr = tid & 127;
    const int j = (int)rank * 128 + jr; // output row (for both seg threads of a pair)

    // ---- load this thread's 128 weights into registers (as 64 packed f32x2)
    unsigned long long w[64];
    {
        const ulonglong2* p =
            (const ulonglong2*)(Wh + (size_t)j * DD + seg * 128);
#pragma unroll
        for (int i = 0; i < 32; i++) {
            ulonglong2 q = p[i];
            w[2 * i] = q.x;
            w[2 * i + 1] = q.y;
        }
    }

    // ---- preload tokens for this batch
    {
        const int4* tp = (const int4*)(tokens + (size_t)b * TT);
        for (int i = tid; i < TT / 4; i += 256) ((int4*)s_tok)[i] = tp[i];
    }
    // ---- h0 = 0
    s_h[0][tid] = 0.f;
    __syncthreads();
    cluster_arrive();
    cluster_wait();

    const unsigned my_h = smem_u32(&s_h[0][0]);
    const unsigned peer_h = mapa_u32(my_h, rank ^ 1);

    const size_t ybase = (size_t)b * TT * DD;
    int p = 0;
    for (int t = 0; t < TT; t++) {
        const int tok = s_tok[t];
        float wx = 0.f, gate = 0.f;
        if (seg == 0) {  // combiner threads prefetch their LUT rows (L2-hot)
            wx = __ldg(&g_WxE[(size_t)tok * DD + j]);
            gate = __ldg(&g_GateE[(size_t)tok * DD + j]);
        }

        // register-resident half matvec: acc = sum_k w[k] * h[seg*128 + k]
        unsigned long long acc0 = 0ull, acc1 = 0ull;
        const unsigned long long* hp =
            (const unsigned long long*)&s_h[p][seg * 128];
#pragma unroll
        for (int i = 0; i < 64; i += 2) {
            acc0 = ffma2(w[i], hp[i], acc0);
            acc1 = ffma2(w[i + 1], hp[i + 1], acc1);
        }
        float2 a0 = unpackf2(acc0);
        float2 a1 = unpackf2(acc1);
        const float acc = (a0.x + a0.y) + (a1.x + a1.y);

        if (seg) s_part[jr] = acc;
        __syncthreads();

        if (seg == 0) {
            const float s = wx + acc + s_part[jr];
            const float hn = tanhf(s);
            s_h[p ^ 1][j] = hn;                                   // local copy
            st_cluster_f32(peer_h + ((unsigned)(p ^ 1) * DD + j) * 4u, hn); // peer copy
            g_Y[ybase + (size_t)t * DD + j] = hn * gate;          // gated output
        }
        cluster_arrive();   // release: DSMEM + local h stores ordered before...
        cluster_wait();     // ...acquire in both CTAs for next step's reads
        p ^= 1;
    }
}

// ---------------------------------------------------------------------------
// Kernel C: logits = Y[131072, 256] @ E^T.  Tiled SIMT fp32 GEMM, f32x2 packed.
// Block: 256 threads, tile M=64 x N=256(full), K-chunks of 32.
// Thread micro-tile: 4 rows x 16 cols (as 8 packed col-pairs).
// ---------------------------------------------------------------------------
__global__ void __launch_bounds__(256) head_kernel(
    const float* __restrict__ E, float* __restrict__ out) {
    __shared__ __align__(16) float sY[64][33];     // [m][k], +1 pad
    __shared__ __align__(16) float sEt[32][258];   // [k][v], +2 pad (8B rows)

    const int m0 = blockIdx.x * 64;
    const int tid = threadIdx.x;
    const int tm = tid >> 4;   // 16 row-groups of 4
    const int tn = tid & 15;   // 16 col-groups of 16

    unsigned long long acc[4][8];
#pragma unroll
    for (int i = 0; i < 4; i++)
#pragma unroll
        for (int c = 0; c < 8; c++) acc[i][c] = 0ull;

    for (int k0 = 0; k0 < DD; k0 += 32) {
        __syncthreads();
        // ---- load Y tile [64 x 32] (512 float4, 2/thread), store [m][k]
#pragma unroll
        for (int i = 0; i < 2; i++) {
            int idx = tid + i * 256;       // 0..511
            int m = idx >> 3, kq = idx & 7;
            float4 v = *(const float4*)&g_Y[(size_t)(m0 + m) * DD + k0 + kq * 4];
            sY[m][kq * 4 + 0] = v.x;
            sY[m][kq * 4 + 1] = v.y;
            sY[m][kq * 4 + 2] = v.z;
            sY[m][kq * 4 + 3] = v.w;
        }
        // ---- load E chunk [256v x 32k] transposed to [k][v] (2048 float4, 8/thread)
#pragma unroll
        for (int i = 0; i < 8; i++) {
            int idx = i * 256 + tid;
            int v = idx >> 3, kq = idx & 7;
            float4 e4 = *(const float4*)&E[(size_t)v * DD + k0 + kq * 4];
            sEt[kq * 4 + 0][v] = e4.x;
            sEt[kq * 4 + 1][v] = e4.y;
            sEt[kq * 4 + 2][v] = e4.z;
            sEt[kq * 4 + 3][v] = e4.w;
        }
        __syncthreads();

#pragma unroll
        for (int k = 0; k < 32; k++) {
            const float a0 = sY[tm * 4 + 0][k];
            const float a1 = sY[tm * 4 + 1][k];
            const float a2 = sY[tm * 4 + 2][k];
            const float a3 = sY[tm * 4 + 3][k];
            const unsigned long long ap0 = packf2(a0, a0);
            const unsigned long long ap1 = packf2(a1, a1);
            const unsigned long long ap2 = packf2(a2, a2);
            const unsigned long long ap3 = packf2(a3, a3);
            const unsigned long long* bp =
                (const unsigned long long*)&sEt[k][tn * 16];
#pragma unroll
            for (int c = 0; c < 8; c++) {
                const unsigned long long bv = bp[c];
                acc[0][c] = ffma2(ap0, bv, acc[0][c]);
                acc[1][c] = ffma2(ap1, bv, acc[1][c]);
                acc[2][c] = ffma2(ap2, bv, acc[2][c]);
                acc[3][c] = ffma2(ap3, bv, acc[3][c]);
            }
        }
    }

    // ---- writeback: rows m0+tm*4+i, cols tn*16 + {2c, 2c+1}
#pragma unroll
    for (int i = 0; i < 4; i++) {
        float* orow = out + (size_t)(m0 + tm * 4 + i) * VV + tn * 16;
#pragma unroll
        for (int c = 0; c < 8; c++) {
            float2 v = unpackf2(acc[i][c]);
            *(float2*)&orow[2 * c] = v;
        }
    }
}

// ---------------------------------------------------------------------------
extern "C" void kernel_launch(void* const* d_in, const int* in_sizes, int n_in,
                              void* d_out, int out_size) {
    const int* tokens = (const int*)d_in[0];
    const float* E = (const float*)d_in[1];
    const float* Wx = (const float*)d_in[2];
    const float* Wh = (const float*)d_in[3];
    const float* Wz = (const float*)d_in[4];
    float* out = (float*)d_out;

    precompute_kernel<<<VV / 8, 256>>>(E, Wx, Wz);
    rnn_kernel<<<BB * 2, 256>>>(tokens, Wh);           // 64 clusters x 2 CTAs
    head_kernel<<<(BB * TT) / 64, 256>>>(E, out);
}

// round 5
// speedup vs baseline: 2.1314x; 2.1314x over previous
#include <cuda_runtime.h>
#include <math.h>

// Problem constants
#define BB 64
#define TT 2048
#define DD 256
#define VV 256

// Scratch (device globals: allocation-free per harness rules)
__device__ float g_WxE[VV * DD];                       // [v][e]  = E[v] @ Wx^T
__device__ float g_GateE[VV * DD];                     // [v][e]  = sigmoid(E[v] @ Wz^T)
__device__ float g_Y[(long long)BB * TT * DD];         // [b][t][d] = h_t * gate_t  (128 MB)

// ---------------------------------------------------------------------------
// Packed fp32x2 helpers
// ---------------------------------------------------------------------------
__device__ __forceinline__ unsigned long long ffma2(unsigned long long a,
                                                    unsigned long long b,
                                                    unsigned long long c) {
    unsigned long long d;
    asm("fma.rn.f32x2 %0, %1, %2, %3;" : "=l"(d) : "l"(a), "l"(b), "l"(c));
    return d;
}
__device__ __forceinline__ unsigned long long packf2(float lo, float hi) {
    unsigned long long d;
    asm("mov.b64 %0, {%1, %2};" : "=l"(d) : "f"(lo), "f"(hi));
    return d;
}
__device__ __forceinline__ float2 unpackf2(unsigned long long v) {
    float lo, hi;
    asm("mov.b64 {%0, %1}, %2;" : "=f"(lo), "=f"(hi) : "l"(v));
    return make_float2(lo, hi);
}

// ---------------------------------------------------------------------------
// Cluster / mbarrier helpers
// ---------------------------------------------------------------------------
__device__ __forceinline__ unsigned smem_u32(const void* p) {
    return (unsigned)__cvta_generic_to_shared(p);
}
__device__ __forceinline__ unsigned mapa_u32(unsigned addr, unsigned rank) {
    unsigned r;
    asm("mapa.shared::cluster.u32 %0, %1, %2;" : "=r"(r) : "r"(addr), "r"(rank));
    return r;
}
__device__ __forceinline__ unsigned cluster_rank() {
    unsigned r;
    asm("mov.u32 %0, %%cluster_ctarank;" : "=r"(r));
    return r;
}
__device__ __forceinline__ void cluster_sync() {
    asm volatile("barrier.cluster.arrive.aligned;" ::: "memory");
    asm volatile("barrier.cluster.wait.aligned;" ::: "memory");
}
__device__ __forceinline__ void mbar_init(unsigned addr, unsigned count) {
    asm volatile("mbarrier.init.shared.b64 [%0], %1;" :: "r"(addr), "r"(count) : "memory");
}
__device__ __forceinline__ void mbar_arrive_expect_tx(unsigned addr, unsigned bytes) {
    asm volatile("mbarrier.arrive.expect_tx.shared.b64 _, [%0], %1;"
                 :: "r"(addr), "r"(bytes) : "memory");
}
__device__ __forceinline__ void mbar_wait(unsigned addr, unsigned parity) {
    asm volatile(
        "{\n\t"
        ".reg .pred P;\n\t"
        "WAIT_%=:\n\t"
        "mbarrier.try_wait.parity.acquire.cta.shared::cta.b64 P, [%0], %1, 0x989680;\n\t"
        "@P bra.uni DONE_%=;\n\t"
        "bra.uni WAIT_%=;\n\t"
        "DONE_%=:\n\t"
        "}"
        :: "r"(addr), "r"(parity) : "memory");
}
// Async remote-smem store; signals complete_tx (4 bytes) on the remote mbarrier.
__device__ __forceinline__ void st_async_f32(unsigned raddr, float v, unsigned rbar) {
    asm volatile(
        "st.async.shared::cluster.mbarrier::complete_tx::bytes.f32 [%0], %1, [%2];"
        :: "r"(raddr), "f"(v), "r"(rbar) : "memory");
}

// Fast accurate tanh: tanh(x) = sign(x) * (1-e)/(1+e), e = exp(-2|x|). ~3e-7 rel err.
__device__ __forceinline__ float fast_tanh(float x) {
    float ax = fabsf(x);
    float e = __expf(-2.0f * ax);
    float r = __fdividef(1.0f - e, 1.0f + e);
    return copysignf(r, x);
}

// ---------------------------------------------------------------------------
// Kernel A: token-indexed projection LUTs.
// ---------------------------------------------------------------------------
__global__ void __launch_bounds__(256) precompute_kernel(
    const float* __restrict__ E, const float* __restrict__ Wx,
    const float* __restrict__ Wz) {
    __shared__ __align__(16) float sE[8][DD];
    const int v0 = blockIdx.x * 8;
    const int tid = threadIdx.x;

    for (int i = tid; i < 8 * DD / 4; i += 256)
        ((float4*)&sE[0][0])[i] = ((const float4*)(E + (size_t)v0 * DD))[i];
    __syncthreads();

    const int e = tid;
    float awx[8], awz[8];
#pragma unroll
    for (int v = 0; v < 8; v++) { awx[v] = 0.f; awz[v] = 0.f; }

    const float4* wxr = (const float4*)(Wx + (size_t)e * DD);
    const float4* wzr = (const float4*)(Wz + (size_t)e * DD);
#pragma unroll 4
    for (int dq = 0; dq < DD / 4; dq++) {
        float4 x4 = wxr[dq];
        float4 z4 = wzr[dq];
#pragma unroll
        for (int v = 0; v < 8; v++) {
            float4 e4 = *(const float4*)&sE[v][dq * 4];
            awx[v] = fmaf(x4.x, e4.x, awx[v]);
            awx[v] = fmaf(x4.y, e4.y, awx[v]);
            awx[v] = fmaf(x4.z, e4.z, awx[v]);
            awx[v] = fmaf(x4.w, e4.w, awx[v]);
            awz[v] = fmaf(z4.x, e4.x, awz[v]);
            awz[v] = fmaf(z4.y, e4.y, awz[v]);
            awz[v] = fmaf(z4.z, e4.z, awz[v]);
            awz[v] = fmaf(z4.w, e4.w, awz[v]);
        }
    }
#pragma unroll
    for (int v = 0; v < 8; v++) {
        g_WxE[(size_t)(v0 + v) * DD + e] = awx[v];
        g_GateE[(size_t)(v0 + v) * DD + e] = 1.f / (1.f + expf(-awz[v]));
    }
}

// ---------------------------------------------------------------------------
// Kernel B: the recurrence. One 2-CTA cluster per batch (grid 128, block 256).
// CTA rank r holds Wh rows [r*128, r*128+128) in REGISTERS.
// Lane pairing: lane 2m handles half-dot over h[0:128], lane 2m+1 over h[128:256],
// both for output row j = rank*128 + warp*16 + m. shfl.bfly combines.
// Peer h-half exchanged via st.async + mbarrier (no cluster barrier, no L1 flush).
// h layout in smem: s_h[buf][seg][132] (4-float pad kills LDS bank conflicts
// between even/odd lanes reading the two segs).
// ---------------------------------------------------------------------------
__global__ void __launch_bounds__(256, 1) __cluster_dims__(2, 1, 1)
rnn_kernel(const int* __restrict__ tokens, const float* __restrict__ Wh) {
    __shared__ __align__(16) float s_h[2][2][132];   // [buf][seg][128+pad]
    __shared__ __align__(16) int s_tok[TT];
    __shared__ __align__(8) unsigned long long s_bar[2];  // one mbarrier per buf

    const unsigned rank = cluster_rank();
    const int b = blockIdx.x >> 1;
    const int tid = threadIdx.x;
    const int warp = tid >> 5;
    const int lane = tid & 31;
    const int m = lane >> 1;           // pair index within warp
    const int seg = lane & 1;          // which h-half this thread dots
    const int j_local = warp * 16 + m; // output row within this CTA's half
    const int j = (int)rank * 128 + j_local;

    // ---- weights for (row j, h-half seg) into registers: 64 packed f32x2
    unsigned long long w[64];
    {
        const ulonglong2* wp = (const ulonglong2*)(Wh + (size_t)j * DD + seg * 128);
#pragma unroll
        for (int i = 0; i < 32; i++) {
            ulonglong2 q = wp[i];
            w[2 * i] = q.x;
            w[2 * i + 1] = q.y;
        }
    }

    // ---- tokens for this batch
    {
        const int4* tp = (const int4*)(tokens + (size_t)b * TT);
        for (int i = tid; i < TT / 4; i += 256) ((int4*)s_tok)[i] = tp[i];
    }
    // ---- zero h buffers
    for (int i = tid; i < 2 * 2 * 132; i += 256) ((float*)s_h)[i] = 0.f;

    const unsigned my_base = smem_u32(&s_h[0][0][0]);
    const unsigned my_bar = smem_u32(&s_bar[0]);
    if (tid == 0) {
        mbar_init(my_bar, 1);
        mbar_init(my_bar + 8, 1);
        mbar_arrive_expect_tx(my_bar, 512);      // 128 floats/step from peer
        mbar_arrive_expect_tx(my_bar + 8, 512);
    }
    __syncthreads();
    cluster_sync();  // one-time: mbarrier init + zeroed h visible cluster-wide

    const unsigned peer_base = mapa_u32(my_base, rank ^ 1);
    const unsigned peer_bar = mapa_u32(my_bar, rank ^ 1);

    const size_t ybase = (size_t)b * TT * DD;
    unsigned ph0 = 0, ph1 = 0;  // parity per barrier
    int p = 0;
    for (int t = 0; t < TT; t++) {
        const int tok = s_tok[t];
        float wx = 0.f, gate = 0.f;
        if (seg == 0) {  // L1-hot now (no per-step L1 flush)
            wx = __ldg(&g_WxE[(size_t)tok * DD + j]);
            gate = __ldg(&g_GateE[(size_t)tok * DD + j]);
        }

        // half matvec: 32 LDS.128 + 64 FFMA2, 4 independent chains
        const ulonglong2* hp = (const ulonglong2*)&s_h[p][seg][0];
        unsigned long long a0 = 0ull, a1 = 0ull, a2 = 0ull, a3 = 0ull;
#pragma unroll
        for (int i = 0; i < 32; i += 2) {
            ulonglong2 q0 = hp[i];
            ulonglong2 q1 = hp[i + 1];
            a0 = ffma2(w[2 * i + 0], q0.x, a0);
            a1 = ffma2(w[2 * i + 1], q0.y, a1);
            a2 = ffma2(w[2 * i + 2], q1.x, a2);
            a3 = ffma2(w[2 * i + 3], q1.y, a3);
        }
        float2 f0 = unpackf2(a0), f1 = unpackf2(a1);
        float2 f2 = unpackf2(a2), f3 = unpackf2(a3);
        const float acc = ((f0.x + f0.y) + (f1.x + f1.y)) +
                          ((f2.x + f2.y) + (f3.x + f3.y));
        const float other = __shfl_xor_sync(0xffffffffu, acc, 1);

        const int pn = p ^ 1;
        if (seg == 0) {
            const float s = wx + acc + other;
            const float hn = fast_tanh(s);
            s_h[pn][rank][j_local] = hn;  // local copy of our half
            const unsigned off = (unsigned)((pn * 264 + (int)rank * 132 + j_local) * 4);
            st_async_f32(peer_base + off, hn, peer_bar + (unsigned)pn * 8u);
            g_Y[ybase + (size_t)t * DD + j] = hn * gate;
        }

        // wait for peer's 128 floats into s_h[pn][rank^1][*]
        const unsigned barpn = my_bar + (unsigned)pn * 8u;
        if (pn == 0) { mbar_wait(barpn, ph0); ph0 ^= 1; }
        else         { mbar_wait(barpn, ph1); ph1 ^= 1; }
        if (tid == 0) mbar_arrive_expect_tx(barpn, 512);  // re-arm for t+2
        __syncthreads();  // local half visible + re-arm ordered before next st.async
        p = pn;
    }
    cluster_sync();  // don't exit while peer smem traffic may be in flight
}

// ---------------------------------------------------------------------------
// Kernel C: logits = Y[131072, 256] @ E^T.  Tiled fp32 GEMM, f32x2 packed.
// A operand pre-splatted ((v,v) pairs) in smem: inner loop has zero MOV-packs.
// ---------------------------------------------------------------------------
__global__ void __launch_bounds__(256) head_kernel(
    const float* __restrict__ E, float* __restrict__ out) {
    __shared__ __align__(16) unsigned long long sYp[64][33];  // splatted [m][k]
    __shared__ __align__(16) float sEt[32][258];              // [k][v]

    const int m0 = blockIdx.x * 64;
    const int tid = threadIdx.x;
    const int tm = tid >> 4;   // 16 row-groups of 4
    const int tn = tid & 15;   // 16 col-groups of 16

    unsigned long long acc[4][8];
#pragma unroll
    for (int i = 0; i < 4; i++)
#pragma unroll
        for (int c = 0; c < 8; c++) acc[i][c] = 0ull;

    for (int k0 = 0; k0 < DD; k0 += 32) {
        __syncthreads();
#pragma unroll
        for (int i = 0; i < 2; i++) {
            int idx = tid + i * 256;
            int m = idx >> 3, kq = idx & 7;
            float4 v = *(const float4*)&g_Y[(size_t)(m0 + m) * DD + k0 + kq * 4];
            sYp[m][kq * 4 + 0] = packf2(v.x, v.x);
            sYp[m][kq * 4 + 1] = packf2(v.y, v.y);
            sYp[m][kq * 4 + 2] = packf2(v.z, v.z);
            sYp[m][kq * 4 + 3] = packf2(v.w, v.w);
        }
#pragma unroll
        for (int i = 0; i < 8; i++) {
            int idx = i * 256 + tid;
            int v = idx >> 3, kq = idx & 7;
            float4 e4 = *(const float4*)&E[(size_t)v * DD + k0 + kq * 4];
            sEt[kq * 4 + 0][v] = e4.x;
            sEt[kq * 4 + 1][v] = e4.y;
            sEt[kq * 4 + 2][v] = e4.z;
            sEt[kq * 4 + 3][v] = e4.w;
        }
        __syncthreads();

#pragma unroll
        for (int k = 0; k < 32; k++) {
            const unsigned long long ap0 = sYp[tm * 4 + 0][k];
            const unsigned long long ap1 = sYp[tm * 4 + 1][k];
            const unsigned long long ap2 = sYp[tm * 4 + 2][k];
            const unsigned long long ap3 = sYp[tm * 4 + 3][k];
            const unsigned long long* bp =
                (const unsigned long long*)&sEt[k][tn * 16];
#pragma unroll
            for (int c = 0; c < 8; c++) {
                const unsigned long long bv = bp[c];
                acc[0][c] = ffma2(ap0, bv, acc[0][c]);
                acc[1][c] = ffma2(ap1, bv, acc[1][c]);
                acc[2][c] = ffma2(ap2, bv, acc[2][c]);
                acc[3][c] = ffma2(ap3, bv, acc[3][c]);
            }
        }
    }

#pragma unroll
    for (int i = 0; i < 4; i++) {
        float* orow = out + (size_t)(m0 + tm * 4 + i) * VV + tn * 16;
#pragma unroll
        for (int c = 0; c < 8; c++) {
            float2 v = unpackf2(acc[i][c]);
            *(float2*)&orow[2 * c] = v;
        }
    }
}

// ---------------------------------------------------------------------------
extern "C" void kernel_launch(void* const* d_in, const int* in_sizes, int n_in,
                              void* d_out, int out_size) {
    const int* tokens = (const int*)d_in[0];
    const float* E = (const float*)d_in[1];
    const float* Wx = (const float*)d_in[2];
    const float* Wh = (const float*)d_in[3];
    const float* Wz = (const float*)d_in[4];
    float* out = (float*)d_out;

    precompute_kernel<<<VV / 8, 256>>>(E, Wx, Wz);
    rnn_kernel<<<BB * 2, 256>>>(tokens, Wh);           // 64 clusters x 2 CTAs
    head_kernel<<<(BB * TT) / 64, 256>>>(E, out);
}

// round 6
// speedup vs baseline: 3.0719x; 1.4412x over previous
#include <cuda_runtime.h>
#include <math.h>

// Problem constants
#define BB 64
#define TT 2048
#define DD 256
#define VV 256

// Scratch (device globals: allocation-free per harness rules)
__device__ float g_WxE[VV * DD];                       // [v][e]  = E[v] @ Wx^T
__device__ float g_GateE[VV * DD];                     // [v][e]  = sigmoid(E[v] @ Wz^T)
__device__ float g_Y[(long long)BB * TT * DD];         // [b][t][d] = h_t * gate_t  (128 MB)

// ---------------------------------------------------------------------------
// Packed fp32x2 helpers
// ---------------------------------------------------------------------------
__device__ __forceinline__ unsigned long long ffma2(unsigned long long a,
                                                    unsigned long long b,
                                                    unsigned long long c) {
    unsigned long long d;
    asm("fma.rn.f32x2 %0, %1, %2, %3;" : "=l"(d) : "l"(a), "l"(b), "l"(c));
    return d;
}
__device__ __forceinline__ unsigned long long packf2(float lo, float hi) {
    unsigned long long d;
    asm("mov.b64 %0, {%1, %2};" : "=l"(d) : "f"(lo), "f"(hi));
    return d;
}
__device__ __forceinline__ float2 unpackf2(unsigned long long v) {
    float lo, hi;
    asm("mov.b64 {%0, %1}, %2;" : "=f"(lo), "=f"(hi) : "l"(v));
    return make_float2(lo, hi);
}

// ---------------------------------------------------------------------------
// Cluster / mbarrier helpers
// ---------------------------------------------------------------------------
__device__ __forceinline__ unsigned smem_u32(const void* p) {
    return (unsigned)__cvta_generic_to_shared(p);
}
__device__ __forceinline__ unsigned mapa_u32(unsigned addr, unsigned rank) {
    unsigned r;
    asm("mapa.shared::cluster.u32 %0, %1, %2;" : "=r"(r) : "r"(addr), "r"(rank));
    return r;
}
__device__ __forceinline__ unsigned cluster_rank() {
    unsigned r;
    asm("mov.u32 %0, %%cluster_ctarank;" : "=r"(r));
    return r;
}
__device__ __forceinline__ void cluster_sync() {
    asm volatile("barrier.cluster.arrive.aligned;" ::: "memory");
    asm volatile("barrier.cluster.wait.aligned;" ::: "memory");
}
__device__ __forceinline__ void mbar_init(unsigned addr, unsigned count) {
    asm volatile("mbarrier.init.shared.b64 [%0], %1;" :: "r"(addr), "r"(count) : "memory");
}
__device__ __forceinline__ void mbar_arrive_expect_tx(unsigned addr, unsigned bytes) {
    asm volatile("mbarrier.arrive.expect_tx.shared.b64 _, [%0], %1;"
                 :: "r"(addr), "r"(bytes) : "memory");
}
__device__ __forceinline__ void mbar_wait(unsigned addr, unsigned parity) {
    asm volatile(
        "{\n\t"
        ".reg .pred P;\n\t"
        "WAIT_%=:\n\t"
        "mbarrier.try_wait.parity.acquire.cta.shared::cta.b64 P, [%0], %1, 0x989680;\n\t"
        "@P bra.uni DONE_%=;\n\t"
        "bra.uni WAIT_%=;\n\t"
        "DONE_%=:\n\t"
        "}"
        :: "r"(addr), "r"(parity) : "memory");
}
// One-shot bulk SMEM->peer-SMEM copy; signals complete_tx(bytes) on remote mbar.
__device__ __forceinline__ void bulk_copy_cluster(unsigned dst_cluster,
                                                  unsigned src_cta,
                                                  unsigned bytes,
                                                  unsigned rbar_cluster) {
    asm volatile(
        "cp.async.bulk.shared::cluster.shared::cta.mbarrier::complete_tx::bytes "
        "[%0], [%1], %2, [%3];"
        :: "r"(dst_cluster), "r"(src_cta), "r"(bytes), "r"(rbar_cluster)
        : "memory");
}
__device__ __forceinline__ void fence_proxy_async_cta() {
    asm volatile("fence.proxy.async.shared::cta;" ::: "memory");
}

// Fast accurate tanh: tanh(x) = sign(x) * (1-e)/(1+e), e = exp(-2|x|). ~3e-7 rel err.
__device__ __forceinline__ float fast_tanh(float x) {
    float ax = fabsf(x);
    float e = __expf(-2.0f * ax);
    float r = __fdividef(1.0f - e, 1.0f + e);
    return copysignf(r, x);
}

// ---------------------------------------------------------------------------
// Kernel A: token-indexed projection LUTs.
// ---------------------------------------------------------------------------
__global__ void __launch_bounds__(256) precompute_kernel(
    const float* __restrict__ E, const float* __restrict__ Wx,
    const float* __restrict__ Wz) {
    __shared__ __align__(16) float sE[8][DD];
    const int v0 = blockIdx.x * 8;
    const int tid = threadIdx.x;

    for (int i = tid; i < 8 * DD / 4; i += 256)
        ((float4*)&sE[0][0])[i] = ((const float4*)(E + (size_t)v0 * DD))[i];
    __syncthreads();

    const int e = tid;
    float awx[8], awz[8];
#pragma unroll
    for (int v = 0; v < 8; v++) { awx[v] = 0.f; awz[v] = 0.f; }

    const float4* wxr = (const float4*)(Wx + (size_t)e * DD);
    const float4* wzr = (const float4*)(Wz + (size_t)e * DD);
#pragma unroll 4
    for (int dq = 0; dq < DD / 4; dq++) {
        float4 x4 = wxr[dq];
        float4 z4 = wzr[dq];
#pragma unroll
        for (int v = 0; v < 8; v++) {
            float4 e4 = *(const float4*)&sE[v][dq * 4];
            awx[v] = fmaf(x4.x, e4.x, awx[v]);
            awx[v] = fmaf(x4.y, e4.y, awx[v]);
            awx[v] = fmaf(x4.z, e4.z, awx[v]);
            awx[v] = fmaf(x4.w, e4.w, awx[v]);
            awz[v] = fmaf(z4.x, e4.x, awz[v]);
            awz[v] = fmaf(z4.y, e4.y, awz[v]);
            awz[v] = fmaf(z4.z, e4.z, awz[v]);
            awz[v] = fmaf(z4.w, e4.w, awz[v]);
        }
    }
#pragma unroll
    for (int v = 0; v < 8; v++) {
        g_WxE[(size_t)(v0 + v) * DD + e] = awx[v];
        g_GateE[(size_t)(v0 + v) * DD + e] = 1.f / (1.f + expf(-awz[v]));
    }
}

// ---------------------------------------------------------------------------
// Kernel B: the recurrence. One 2-CTA cluster per batch (grid 128, block 256).
// CTA rank r holds Wh rows [r*128, r*128+128) in REGISTERS.
// Lane pairing: lane 2m dots h[0:128], lane 2m+1 dots h[128:256], both for
// row j = rank*128 + warp*16 + m; shfl.bfly combines.
// Exchange: even lanes STS hn to local staging s_h[pn][rank][*]; one
// __syncthreads; tid0 issues ONE 512B cp.async.bulk to the peer's
// s_h[pn][rank][*] signalling the peer's mbarrier (single complete_tx vs 128
// tiny st.async messages in the previous version).
// ---------------------------------------------------------------------------
__global__ void __launch_bounds__(256, 1) __cluster_dims__(2, 1, 1)
rnn_kernel(const int* __restrict__ tokens, const float* __restrict__ Wh) {
    __shared__ __align__(16) float s_h[2][2][132];   // [buf][half][128+pad]
    __shared__ __align__(16) int s_tok[TT];
    __shared__ __align__(8) unsigned long long s_bar[2];  // one mbarrier per buf

    const unsigned rank = cluster_rank();
    const int b = blockIdx.x >> 1;
    const int tid = threadIdx.x;
    const int warp = tid >> 5;
    const int lane = tid & 31;
    const int m = lane >> 1;           // pair index within warp
    const int seg = lane & 1;          // which h-half this thread dots
    const int j_local = warp * 16 + m; // output row within this CTA's half
    const int j = (int)rank * 128 + j_local;

    // ---- weights for (row j, h-half seg) into registers: 64 packed f32x2
    unsigned long long w[64];
    {
        const ulonglong2* wp = (const ulonglong2*)(Wh + (size_t)j * DD + seg * 128);
#pragma unroll
        for (int i = 0; i < 32; i++) {
            ulonglong2 q = wp[i];
            w[2 * i] = q.x;
            w[2 * i + 1] = q.y;
        }
    }

    // ---- tokens for this batch
    {
        const int4* tp = (const int4*)(tokens + (size_t)b * TT);
        for (int i = tid; i < TT / 4; i += 256) ((int4*)s_tok)[i] = tp[i];
    }
    // ---- zero h buffers
    for (int i = tid; i < 2 * 2 * 132; i += 256) ((float*)s_h)[i] = 0.f;

    const unsigned my_base = smem_u32(&s_h[0][0][0]);
    const unsigned my_bar = smem_u32(&s_bar[0]);
    if (tid == 0) {
        mbar_init(my_bar, 1);
        mbar_init(my_bar + 8, 1);
        mbar_arrive_expect_tx(my_bar, 512);      // 512B/step from peer
        mbar_arrive_expect_tx(my_bar + 8, 512);
    }
    __syncthreads();
    cluster_sync();  // one-time: mbarrier init + zeroed h visible cluster-wide

    const unsigned peer_base = mapa_u32(my_base, rank ^ 1);
    const unsigned peer_bar = mapa_u32(my_bar, rank ^ 1);
    // byte offset of staging region for buffer pn (our global half = rank)
    const unsigned stg_off0 = (unsigned)((0 * 264 + (int)rank * 132) * 4);
    const unsigned stg_off1 = (unsigned)((1 * 264 + (int)rank * 132) * 4);

    const size_t ybase = (size_t)b * TT * DD;
    unsigned ph0 = 0, ph1 = 0;  // parity per barrier

    // LUT prefetch (one step ahead, register double-buffer)
    float wx = 0.f, gate = 0.f;
    if (seg == 0) {
        const int tok0 = s_tok[0];
        wx = __ldg(&g_WxE[(size_t)tok0 * DD + j]);
        gate = __ldg(&g_GateE[(size_t)tok0 * DD + j]);
    }

    int p = 0;
    for (int t = 0; t < TT; t++) {
        // prefetch t+1 LUT rows (off critical path; hidden under matvec)
        float wx_n = 0.f, gate_n = 0.f;
        if (seg == 0) {
            const int tok_n = s_tok[(t + 1 < TT) ? (t + 1) : t];
            wx_n = __ldg(&g_WxE[(size_t)tok_n * DD + j]);
            gate_n = __ldg(&g_GateE[(size_t)tok_n * DD + j]);
        }

        // half matvec: 32 LDS.128 + 64 FFMA2, 4 independent chains
        const ulonglong2* hp = (const ulonglong2*)&s_h[p][seg][0];
        unsigned long long a0 = 0ull, a1 = 0ull, a2 = 0ull, a3 = 0ull;
#pragma unroll
        for (int i = 0; i < 32; i += 2) {
            ulonglong2 q0 = hp[i];
            ulonglong2 q1 = hp[i + 1];
            a0 = ffma2(w[2 * i + 0], q0.x, a0);
            a1 = ffma2(w[2 * i + 1], q0.y, a1);
            a2 = ffma2(w[2 * i + 2], q1.x, a2);
            a3 = ffma2(w[2 * i + 3], q1.y, a3);
        }
        float2 f0 = unpackf2(a0), f1 = unpackf2(a1);
        float2 f2 = unpackf2(a2), f3 = unpackf2(a3);
        const float acc = ((f0.x + f0.y) + (f1.x + f1.y)) +
                          ((f2.x + f2.y) + (f3.x + f3.y));
        const float other = __shfl_xor_sync(0xffffffffu, acc, 1);

        const int pn = p ^ 1;
        if (seg == 0) {
            const float s = wx + acc + other;
            const float hn = fast_tanh(s);
            s_h[pn][rank][j_local] = hn;              // local staging (= local copy)
            g_Y[ybase + (size_t)t * DD + j] = hn * gate;
        }
        __syncthreads();  // staging complete (also: all warps done reading s_h[p])

        const unsigned off = pn ? stg_off1 : stg_off0;
        if (tid == 0) {
            fence_proxy_async_cta();  // order generic STS before async-proxy read
            bulk_copy_cluster(peer_base + off, my_base + off, 512,
                              peer_bar + (unsigned)pn * 8u);
        }

        // wait for peer's 512B into s_h[pn][rank^1][*]
        const unsigned barpn = my_bar + (unsigned)pn * 8u;
        if (pn == 0) { mbar_wait(barpn, ph0); ph0 ^= 1; }
        else         { mbar_wait(barpn, ph1); ph1 ^= 1; }
        if (tid == 0) mbar_arrive_expect_tx(barpn, 512);  // re-arm for t+2

        wx = wx_n; gate = gate_n;
        p = pn;
    }
    cluster_sync();  // don't exit while peer smem traffic may be in flight
}

// ---------------------------------------------------------------------------
// Kernel C: logits = Y[131072, 256] @ E^T.  Tiled fp32 GEMM, f32x2 packed.
// Block tile 128x256, 256 threads, micro-tile 8x16.
// tm = tid&15 (16 row slots), tn = tid>>4 (16 col groups).
// Thread rows: tm + 16*i (strided!) -> A-operand LDS bank = (tm+16i+k)%32,
// conflict-free across the warp. B-operand: 2 broadcast groups per warp.
// ---------------------------------------------------------------------------
__global__ void __launch_bounds__(256) head_kernel(
    const float* __restrict__ E, float* __restrict__ out) {
    __shared__ __align__(16) float sY[128][33];    // [m][k]
    __shared__ __align__(16) float sEt[32][258];   // [k][v]

    const int m0 = blockIdx.x * 128;
    const int tid = threadIdx.x;
    const int tm = tid & 15;   // row slot: rows tm + 16*i
    const int tn = tid >> 4;   // col group: cols [tn*16, tn*16+16)

    unsigned long long acc[8][8];
#pragma unroll
    for (int i = 0; i < 8; i++)
#pragma unroll
        for (int c = 0; c < 8; c++) acc[i][c] = 0ull;

    for (int k0 = 0; k0 < DD; k0 += 32) {
        __syncthreads();
        // ---- load Y tile [128 x 32] (1024 float4, 4/thread)
#pragma unroll
        for (int i = 0; i < 4; i++) {
            int idx = tid + i * 256;       // 0..1023
            int mm = idx >> 3, kq = idx & 7;
            float4 v = *(const float4*)&g_Y[(size_t)(m0 + mm) * DD + k0 + kq * 4];
            sY[mm][kq * 4 + 0] = v.x;
            sY[mm][kq * 4 + 1] = v.y;
            sY[mm][kq * 4 + 2] = v.z;
            sY[mm][kq * 4 + 3] = v.w;
        }
        // ---- load E chunk [256v x 32k] transposed to [k][v] (2048 float4, 8/thread)
#pragma unroll
        for (int i = 0; i < 8; i++) {
            int idx = i * 256 + tid;
            int v = idx >> 3, kq = idx & 7;
            float4 e4 = *(const float4*)&E[(size_t)v * DD + k0 + kq * 4];
            sEt[kq * 4 + 0][v] = e4.x;
            sEt[kq * 4 + 1][v] = e4.y;
            sEt[kq * 4 + 2][v] = e4.z;
            sEt[kq * 4 + 3][v] = e4.w;
        }
        __syncthreads();

#pragma unroll
        for (int k = 0; k < 32; k++) {
            unsigned long long ap[8];
#pragma unroll
            for (int i = 0; i < 8; i++) {
                const float a = sY[tm + 16 * i][k];
                ap[i] = packf2(a, a);
            }
            const unsigned long long* bp =
                (const unsigned long long*)&sEt[k][tn * 16];
            unsigned long long bv[8];
#pragma unroll
            for (int c = 0; c < 8; c++) bv[c] = bp[c];
#pragma unroll
            for (int i = 0; i < 8; i++)
#pragma unroll
                for (int c = 0; c < 8; c++)
                    acc[i][c] = ffma2(ap[i], bv[c], acc[i][c]);
        }
    }

    // ---- writeback: rows m0 + tm + 16*i, cols tn*16 + {2c, 2c+1}
#pragma unroll
    for (int i = 0; i < 8; i++) {
        float* orow = out + (size_t)(m0 + tm + 16 * i) * VV + tn * 16;
#pragma unroll
        for (int c = 0; c < 8; c++) {
            float2 v = unpackf2(acc[i][c]);
            *(float2*)&orow[2 * c] = v;
        }
    }
}

// ---------------------------------------------------------------------------
extern "C" void kernel_launch(void* const* d_in, const int* in_sizes, int n_in,
                              void* d_out, int out_size) {
    const int* tokens = (const int*)d_in[0];
    const float* E = (const float*)d_in[1];
    const float* Wx = (const float*)d_in[2];
    const float* Wh = (const float*)d_in[3];
    const float* Wz = (const float*)d_in[4];
    float* out = (float*)d_out;

    precompute_kernel<<<VV / 8, 256>>>(E, Wx, Wz);
    rnn_kernel<<<BB * 2, 256>>>(tokens, Wh);           // 64 clusters x 2 CTAs
    head_kernel<<<(BB * TT) / 128, 256>>>(E, out);
}